// round 5
// baseline (speedup 1.0000x reference)
#include <cuda_runtime.h>
#include <math.h>

#define MM      128
#define MP1     129
#define DD      24
#define NN      512
#define LL      256
#define MSTRIDE 132

#define NULLF   (-1.0e30f)
#define LOG2E   1.4426950408889634f
#define LN2     0.6931471805599453f

// ---------------- device-global scratch (all log2 domain) ----------------
__device__ __align__(16) float g_cb0[MSTRIDE];
__device__ __align__(16) float g_cb1[MSTRIDE];
__device__ __align__(16) float g_w  [MSTRIDE];
__device__ __align__(16) float g_q00[MSTRIDE];
__device__ __align__(16) float g_q10[MSTRIDE];
__device__ __align__(16) float g_q01[MSTRIDE];
__device__ __align__(16) float g_q11[MSTRIDE];
__device__ __align__(16) float g_c0 [MSTRIDE];
__device__ __align__(16) float g_c1 [MSTRIDE];
__device__ __align__(16) float g_Ea [(DD + 1) * MSTRIDE];  // +1 zero row for padding
__device__ __align__(16) float g_Ei [(DD + 1) * MSTRIDE];
__device__ __align__(16) int   g_tok[NN * LL];

// ---- fast log2-domain primitives ----
__device__ __forceinline__ float ex2f(float x) {
    float r; asm("ex2.approx.ftz.f32 %0, %1;" : "=f"(r) : "f"(x)); return r;
}
__device__ __forceinline__ float lg2f(float x) {
    float r; asm("lg2.approx.ftz.f32 %0, %1;" : "=f"(r) : "f"(x)); return r;
}
__device__ __forceinline__ float lse2(float a, float b) {
    float m = fmaxf(a, b);
    float d = -fabsf(a - b);
    return m + lg2f(1.0f + ex2f(d));
}
__device__ __forceinline__ float lse3(float a, float b, float c) {
    float m = fmaxf(fmaxf(a, b), c);
    float s = ex2f(a - m) + ex2f(b - m) + ex2f(c - m);
    return m + lg2f(s);
}
__device__ __forceinline__ float lse4(float a, float b, float c, float d) {
    float m = fmaxf(fmaxf(a, b), fmaxf(c, d));
    float s = (ex2f(a - m) + ex2f(b - m)) + (ex2f(c - m) + ex2f(d - m));
    return m + lg2f(s);
}
__device__ __forceinline__ float lse5(float a, float b, float c, float d, float e) {
    float m = fmaxf(fmaxf(fmaxf(a, b), fmaxf(c, d)), e);
    float s = (ex2f(a - m) + ex2f(b - m)) + (ex2f(c - m) + ex2f(d - m)) + ex2f(e - m);
    return m + lg2f(s);
}
__device__ __forceinline__ float lse2_acc(float a, float b) {  // accurate, prep only
    float mx = fmaxf(a, b);
    float mn = fminf(a, b);
    return mx + log1pf(expf(mn - mx));
}

// ---------------- fused prep: blocks 0..NN-1 = tokens, block NN = constants ----------------
__global__ void prep(const float* __restrict__ anc,
                     const float* __restrict__ ins,
                     const float* __restrict__ rr,
                     const float* __restrict__ uu,
                     const float* __restrict__ data) {
    int b = blockIdx.x;
    if (b < NN) {
        int t = threadIdx.x;                       // 0..255
        const float* row = data + ((size_t)(b * LL + t)) * DD;
        int tk = DD;                                // padding -> zero emission row
        for (int d = 0; d < DD; d++)
            if (row[d] > 0.5f) tk = d;
        g_tok[b * LL + t] = tk;
        return;
    }

    int m = threadIdx.x;
    if (m < MSTRIDE) {                              // zero padding row (tk == DD)
        g_Ea[DD * MSTRIDE + m] = 0.f;
        g_Ei[DD * MSTRIDE + m] = 0.f;
    }
    if (m >= MP1) return;

    {
        const float* ar = anc + m * DD;
        float mx = -1e30f;
        for (int d = 0; d < DD; d++) mx = fmaxf(mx, ar[d]);
        float s = 0.f;
        for (int d = 0; d < DD; d++) s += expf(ar[d] - mx);
        float lse = mx + logf(s);
        for (int d = 0; d < DD; d++) g_Ea[d * MSTRIDE + m] = (ar[d] - lse) * LOG2E;
    }
    {
        const float* ir = ins + m * DD;
        float mx = -1e30f;
        for (int d = 0; d < DD; d++) mx = fmaxf(mx, ir[d]);
        float s = 0.f;
        for (int d = 0; d < DD; d++) s += expf(ir[d] - mx);
        float lse = mx + logf(s);
        for (int d = 0; d < DD; d++) g_Ei[d * MSTRIDE + m] = (ir[d] - lse) * LOG2E;
    }

    float r[3][2], u[3][2];
    for (int c = 0; c < 3; c++) {
        float x0 = rr[(m * 3 + c) * 2 + 0];
        float x1 = rr[(m * 3 + c) * 2 + 1];
        float l2 = lse2_acc(x0, x1);
        r[c][0] = x0 - l2; r[c][1] = x1 - l2;
        x0 = uu[(m * 3 + c) * 2 + 0];
        x1 = uu[(m * 3 + c) * 2 + 1];
        l2 = lse2_acc(x0, x1);
        u[c][0] = x0 - l2; u[c][1] = x1 - l2;
    }
    g_w  [m] = (r[2][0] + u[2][1]) * LOG2E;
    g_cb0[m] = (r[0][0] + u[0][1]) * LOG2E;
    g_cb1[m] = (r[1][0] + u[1][1]) * LOG2E;
    g_q00[m] = (r[0][0] + u[0][0]) * LOG2E;
    g_q10[m] = (r[1][0] + u[1][0]) * LOG2E;
    g_q01[m] = (r[0][1]) * LOG2E;
    g_q11[m] = (r[1][1]) * LOG2E;
    g_c0 [m] = (r[2][0] + u[2][0]) * LOG2E;
    g_c1 [m] = (r[2][1]) * LOG2E;
}

// ---------------- main: one warp handles TWO sequences (ILP interleave) ----------------
__global__ void __launch_bounds__(32) hmm_fwd(float* __restrict__ out) {
    const unsigned FULL = 0xffffffffu;
    const int nA = blockIdx.x * 2;
    const int nB = nA + 1;
    const int l = threadIdx.x;
    const int m0 = l * 4;
    const bool lastlane = (l == 31);

    // shared per-element constants (one copy for both sequences)
    float cb0[4], cb1[4], wv[4], q00[4], q10[4], q01[4], q11[4], c0[4], c1[4];
#pragma unroll
    for (int q = 0; q < 4; q++) {
        int m = m0 + q;
        cb0[q] = g_cb0[m]; cb1[q] = g_cb1[m]; wv[q] = g_w[m];
        q00[q] = g_q00[m]; q10[q] = g_q10[m];
        q01[q] = g_q01[m]; q11[q] = g_q11[m];
        c0[q]  = g_c0[m];  c1[q]  = g_c1[m];
    }
    const float q00x = lastlane ? g_q00[MM] : NULLF;
    const float q10x = lastlane ? g_q10[MM] : NULLF;
    const float q01x = lastlane ? g_q01[MM] : NULLF;
    const float q11x = lastlane ? g_q11[MM] : NULLF;
    const float c0x  = lastlane ? g_c0 [MM] : NULLF;
    const float c1x  = lastlane ? g_c1 [MM] : NULLF;

    const float wv0 = wv[0], wv1 = wv[1], wv2 = wv[2], wv3 = wv[3];
    const float W23  = wv2 + wv3;
    const float W12  = wv1 + wv2;
    const float Wp1  = wv0 + wv1;
    const float Wp2  = Wp1 + wv2;
    const float W123 = wv1 + W23;
    const float cbW0 = cb0[0] + W123;
    const float cbW1 = cb1[0] + W123;
    const float Lw   = wv0 + W123;

    // inclusive prefix P (once)
    float P = Lw;
#pragma unroll
    for (int d = 1; d < 32; d <<= 1) {
        float o = __shfl_up_sync(FULL, P, d);
        if (l >= d) P += o;
    }
    float Pm1  = __shfl_up_sync(FULL, P, 1);
    float Pm2  = __shfl_up_sync(FULL, P, 2);
    float Pm3  = __shfl_up_sync(FULL, P, 3);
    float Pm4  = __shfl_up_sync(FULL, P, 4);
    float Pm8  = __shfl_up_sync(FULL, P, 8);
    float Pm12 = __shfl_up_sync(FULL, P, 12);
    float Pm16 = __shfl_up_sync(FULL, P, 16);
    const float K01 = (l >= 1 ) ? P - Pm1  : NULLF;
    const float K02 = (l >= 2 ) ? P - Pm2  : NULLF;
    const float K03 = (l >= 3 ) ? P - Pm3  : NULLF;
    const float K11 = (l >= 4 ) ? P - Pm4  : NULLF;
    const float K12 = (l >= 8 ) ? P - Pm8  : NULLF;
    const float K13 = (l >= 12) ? P - Pm12 : NULLF;
    const float K21 = (l >= 16) ? P - Pm16 : NULLF;

    // per-sequence state
    float Aa0[4] = {NULLF, NULLF, NULLF, NULLF};
    float Aa1[4] = {NULLF, NULLF, NULLF, NULLF};
    float Aa0x = NULLF, Aa1x = NULLF, Asrc = 0.0f;
    float Ba0[4] = {NULLF, NULLF, NULLF, NULLF};
    float Ba1[4] = {NULLF, NULLF, NULLF, NULLF};
    float Ba0x = NULLF, Ba1x = NULLF, Bsrc = 0.0f;

    const int* tnA = g_tok + nA * LL;
    const int* tnB = g_tok + nB * LL;

    // one HMM step for one sequence (all constants captured by reference)
    auto step = [&](float (&a0)[4], float (&a1)[4], float& a0x, float& a1x,
                    float& lane0src, int tko) {
        float atop = __shfl_up_sync(FULL, a0[3], 1);
        if (l == 0) atop = lane0src;

        float b0 = lse2(atop  + cb0[0], a1[0] + cb1[0]);
        float b1 = lse2(a0[0] + cb0[1], a1[1] + cb1[1]);
        float b2 = lse2(a0[1] + cb0[2], a1[2] + cb1[2]);
        float b3 = lse2(a0[2] + cb0[3], a1[3] + cb1[3]);

        float Bs = lse5(atop + cbW0, a1[0] + cbW1, b1 + W23, b2 + wv3, b3);

        float o1 = __shfl_up_sync(FULL, Bs, 1);
        float o2 = __shfl_up_sync(FULL, Bs, 2);
        float o3 = __shfl_up_sync(FULL, Bs, 3);
        Bs = lse4(Bs, o1 + K01, o2 + K02, o3 + K03);
        o1 = __shfl_up_sync(FULL, Bs, 4);
        o2 = __shfl_up_sync(FULL, Bs, 8);
        o3 = __shfl_up_sync(FULL, Bs, 12);
        Bs = lse4(Bs, o1 + K11, o2 + K12, o3 + K13);
        o1 = __shfl_up_sync(FULL, Bs, 16);
        Bs = lse2(Bs, o1 + K21);

        float Bex = __shfl_up_sync(FULL, Bs, 1);
        if (l == 0) Bex = NULLF;

        float B1 = lse2(Bex + wv0, b0);
        float B2 = lse3(Bex + Wp1, b0 + wv1, b1);
        float B3 = lse4(Bex + Wp2, b0 + W12, b1 + wv2, b2);

        const float4 ea = *(const float4*)(g_Ea + tko + m0);
        const float4 ei = *(const float4*)(g_Ei + tko + m0);
        const float eax = g_Ea[tko + MM];
        const float eix = g_Ei[tko + MM];

        float na00 = lse3(atop  + q00[0], a1[0] + q10[0], Bex + c0[0]) + ea.x;
        float na10 = lse3(atop  + q01[0], a1[0] + q11[0], Bex + c1[0]) + ei.x;
        float na01 = lse3(a0[0] + q00[1], a1[1] + q10[1], B1  + c0[1]) + ea.y;
        float na11 = lse3(a0[0] + q01[1], a1[1] + q11[1], B1  + c1[1]) + ei.y;
        float na02 = lse3(a0[1] + q00[2], a1[2] + q10[2], B2  + c0[2]) + ea.z;
        float na12 = lse3(a0[1] + q01[2], a1[2] + q11[2], B2  + c1[2]) + ei.z;
        float na03 = lse3(a0[2] + q00[3], a1[3] + q10[3], B3  + c0[3]) + ea.w;
        float na13 = lse3(a0[2] + q01[3], a1[3] + q11[3], B3  + c1[3]) + ei.w;
        float na0x = lse3(a0[3] + q00x, a1x + q10x, Bs + c0x) + eax;
        float na1x = lse3(a0[3] + q01x, a1x + q11x, Bs + c1x) + eix;

        a0[0] = na00; a0[1] = na01; a0[2] = na02; a0[3] = na03;
        a1[0] = na10; a1[1] = na11; a1[2] = na12; a1[3] = na13;
        a0x = na0x; a1x = na1x;
        lane0src = NULLF;
    };

    for (int tt = 0; tt < LL; tt += 4) {
        const int4 tkA = *(const int4*)(tnA + tt);
        const int4 tkB = *(const int4*)(tnB + tt);
        const int tksA[4] = {tkA.x, tkA.y, tkA.z, tkA.w};
        const int tksB[4] = {tkB.x, tkB.y, tkB.z, tkB.w};

#pragma unroll
        for (int k = 0; k < 4; k++) {
            step(Aa0, Aa1, Aa0x, Aa1x, Asrc, tksA[k] * MSTRIDE);
            step(Ba0, Ba1, Ba0x, Ba1x, Bsrc, tksB[k] * MSTRIDE);
        }
    }

    // final logsumexp for both sequences
    auto finish = [&](float (&a0)[4], float (&a1)[4], float a0x, float a1x) -> float {
        float mx = fmaxf(a0x, a1x);
#pragma unroll
        for (int q = 0; q < 4; q++) mx = fmaxf(mx, fmaxf(a0[q], a1[q]));
#pragma unroll
        for (int d = 16; d; d >>= 1) mx = fmaxf(mx, __shfl_xor_sync(FULL, mx, d));
        float s = exp2f(a0x - mx) + exp2f(a1x - mx);
#pragma unroll
        for (int q = 0; q < 4; q++) s += exp2f(a0[q] - mx) + exp2f(a1[q] - mx);
#pragma unroll
        for (int d = 16; d; d >>= 1) s += __shfl_xor_sync(FULL, s, d);
        return (mx + log2f(s)) * LN2;
    };

    float rA = finish(Aa0, Aa1, Aa0x, Aa1x);
    float rB = finish(Ba0, Ba1, Ba0x, Ba1x);
    if (l == 0) {
        out[nA] = rA;
        out[nB] = rB;
    }
}

// ---------------- entry point ----------------
extern "C" void kernel_launch(void* const* d_in, const int* in_sizes, int n_in,
                              void* d_out, int out_size) {
    const float* anc  = (const float*)d_in[0];  // (129, 24)
    const float* ins  = (const float*)d_in[1];  // (129, 24)
    const float* rr   = (const float*)d_in[2];  // (129, 3, 2)
    const float* uu   = (const float*)d_in[3];  // (129, 3, 2)
    const float* data = (const float*)d_in[4];  // (512, 256, 24)
    (void)in_sizes; (void)n_in; (void)out_size;

    prep<<<NN + 1, LL>>>(anc, ins, rr, uu, data);
    hmm_fwd<<<NN / 2, 32>>>((float*)d_out);
}

// round 6
// speedup vs baseline: 1.6405x; 1.6405x over previous
#include <cuda_runtime.h>
#include <math.h>

#define MM      128
#define MP1     129
#define DD      24
#define NN      512
#define LL      256
#define MSTRIDE 132

#define NULLF   (-1.0e30f)
#define LOG2E   1.4426950408889634f
#define LN2     0.6931471805599453f

// ---------------- device-global scratch (all log2 domain) ----------------
__device__ __align__(16) float g_cb0[MSTRIDE];
__device__ __align__(16) float g_cb1[MSTRIDE];
__device__ __align__(16) float g_w  [MSTRIDE];
__device__ __align__(16) float g_q00[MSTRIDE];
__device__ __align__(16) float g_q10[MSTRIDE];
__device__ __align__(16) float g_q01[MSTRIDE];
__device__ __align__(16) float g_q11[MSTRIDE];
__device__ __align__(16) float g_c0 [MSTRIDE];
__device__ __align__(16) float g_c1 [MSTRIDE];
__device__ __align__(16) float g_Ea [(DD + 1) * MSTRIDE];  // +1 zero row for padding
__device__ __align__(16) float g_Ei [(DD + 1) * MSTRIDE];
__device__ __align__(16) int   g_tok[NN * LL];

// ---- fast log2-domain primitives ----
__device__ __forceinline__ float ex2f(float x) {
    float r; asm("ex2.approx.ftz.f32 %0, %1;" : "=f"(r) : "f"(x)); return r;
}
__device__ __forceinline__ float lg2f(float x) {
    float r; asm("lg2.approx.ftz.f32 %0, %1;" : "=f"(r) : "f"(x)); return r;
}
__device__ __forceinline__ float lse2(float a, float b) {
    float m = fmaxf(a, b);
    float d = -fabsf(a - b);
    return m + lg2f(1.0f + ex2f(d));
}
__device__ __forceinline__ float lse3(float a, float b, float c) {
    float m = fmaxf(fmaxf(a, b), c);
    float s = ex2f(a - m) + ex2f(b - m) + ex2f(c - m);
    return m + lg2f(s);
}
__device__ __forceinline__ float lse4(float a, float b, float c, float d) {
    float m = fmaxf(fmaxf(a, b), fmaxf(c, d));
    float s = (ex2f(a - m) + ex2f(b - m)) + (ex2f(c - m) + ex2f(d - m));
    return m + lg2f(s);
}
__device__ __forceinline__ float lse5(float a, float b, float c, float d, float e) {
    float m = fmaxf(fmaxf(fmaxf(a, b), fmaxf(c, d)), e);
    float s = (ex2f(a - m) + ex2f(b - m)) + (ex2f(c - m) + ex2f(d - m)) + ex2f(e - m);
    return m + lg2f(s);
}
__device__ __forceinline__ float lse2_acc(float a, float b) {  // accurate, prep only
    float mx = fmaxf(a, b);
    float mn = fminf(a, b);
    return mx + log1pf(expf(mn - mx));
}

// ---------------- fused prep: blocks 0..NN-1 = tokens, block NN = constants ----------------
__global__ void prep(const float* __restrict__ anc,
                     const float* __restrict__ ins,
                     const float* __restrict__ rr,
                     const float* __restrict__ uu,
                     const float* __restrict__ data) {
    int b = blockIdx.x;
    if (b < NN) {
        int t = threadIdx.x;                       // 0..255
        const float* row = data + ((size_t)(b * LL + t)) * DD;
        int tk = DD;                                // padding -> zero emission row
        for (int d = 0; d < DD; d++)
            if (row[d] > 0.5f) tk = d;
        g_tok[b * LL + t] = tk;
        return;
    }

    int m = threadIdx.x;
    if (m < MSTRIDE) {                              // zero padding row (tk == DD)
        g_Ea[DD * MSTRIDE + m] = 0.f;
        g_Ei[DD * MSTRIDE + m] = 0.f;
    }
    if (m >= MP1) return;

    {
        const float* ar = anc + m * DD;
        float mx = -1e30f;
        for (int d = 0; d < DD; d++) mx = fmaxf(mx, ar[d]);
        float s = 0.f;
        for (int d = 0; d < DD; d++) s += expf(ar[d] - mx);
        float lse = mx + logf(s);
        for (int d = 0; d < DD; d++) g_Ea[d * MSTRIDE + m] = (ar[d] - lse) * LOG2E;
    }
    {
        const float* ir = ins + m * DD;
        float mx = -1e30f;
        for (int d = 0; d < DD; d++) mx = fmaxf(mx, ir[d]);
        float s = 0.f;
        for (int d = 0; d < DD; d++) s += expf(ir[d] - mx);
        float lse = mx + logf(s);
        for (int d = 0; d < DD; d++) g_Ei[d * MSTRIDE + m] = (ir[d] - lse) * LOG2E;
    }

    float r[3][2], u[3][2];
    for (int c = 0; c < 3; c++) {
        float x0 = rr[(m * 3 + c) * 2 + 0];
        float x1 = rr[(m * 3 + c) * 2 + 1];
        float l2 = lse2_acc(x0, x1);
        r[c][0] = x0 - l2; r[c][1] = x1 - l2;
        x0 = uu[(m * 3 + c) * 2 + 0];
        x1 = uu[(m * 3 + c) * 2 + 1];
        l2 = lse2_acc(x0, x1);
        u[c][0] = x0 - l2; u[c][1] = x1 - l2;
    }
    g_w  [m] = (r[2][0] + u[2][1]) * LOG2E;
    g_cb0[m] = (r[0][0] + u[0][1]) * LOG2E;
    g_cb1[m] = (r[1][0] + u[1][1]) * LOG2E;
    g_q00[m] = (r[0][0] + u[0][0]) * LOG2E;
    g_q10[m] = (r[1][0] + u[1][0]) * LOG2E;
    g_q01[m] = (r[0][1]) * LOG2E;
    g_q11[m] = (r[1][1]) * LOG2E;
    g_c0 [m] = (r[2][0] + u[2][0]) * LOG2E;
    g_c1 [m] = (r[2][1]) * LOG2E;
}

// ---------------- main: 4 warps per block, one sequence per warp ----------------
__global__ void __launch_bounds__(128) hmm_fwd(float* __restrict__ out) {
    const unsigned FULL = 0xffffffffu;
    const int wid = threadIdx.x >> 5;               // warp in block -> SMSP wid%4
    const int n = blockIdx.x * 4 + wid;             // sequence index
    const int l = threadIdx.x & 31;
    const int m0 = l * 4;
    const bool lastlane = (l == 31);

    // per-element constants
    float cb0[4], cb1[4], wv[4], q00[4], q10[4], q01[4], q11[4], c0[4], c1[4];
#pragma unroll
    for (int q = 0; q < 4; q++) {
        int m = m0 + q;
        cb0[q] = g_cb0[m]; cb1[q] = g_cb1[m]; wv[q] = g_w[m];
        q00[q] = g_q00[m]; q10[q] = g_q10[m];
        q01[q] = g_q01[m]; q11[q] = g_q11[m];
        c0[q]  = g_c0[m];  c1[q]  = g_c1[m];
    }
    const float q00x = lastlane ? g_q00[MM] : NULLF;
    const float q10x = lastlane ? g_q10[MM] : NULLF;
    const float q01x = lastlane ? g_q01[MM] : NULLF;
    const float q11x = lastlane ? g_q11[MM] : NULLF;
    const float c0x  = lastlane ? g_c0 [MM] : NULLF;
    const float c1x  = lastlane ? g_c1 [MM] : NULLF;

    const float wv0 = wv[0], wv1 = wv[1], wv2 = wv[2], wv3 = wv[3];
    const float W23  = wv2 + wv3;
    const float W12  = wv1 + wv2;
    const float Wp1  = wv0 + wv1;
    const float Wp2  = Wp1 + wv2;
    const float W123 = wv1 + W23;
    const float cbW0 = cb0[0] + W123;
    const float cbW1 = cb1[0] + W123;
    const float Lw   = wv0 + W123;

    // inclusive prefix P (once; radix-2 shfl scan)
    float P = Lw;
#pragma unroll
    for (int d = 1; d < 32; d <<= 1) {
        float o = __shfl_up_sync(FULL, P, d);
        if (l >= d) P += o;
    }
    float Pm1  = __shfl_up_sync(FULL, P, 1);
    float Pm2  = __shfl_up_sync(FULL, P, 2);
    float Pm3  = __shfl_up_sync(FULL, P, 3);
    float Pm4  = __shfl_up_sync(FULL, P, 4);
    float Pm8  = __shfl_up_sync(FULL, P, 8);
    float Pm12 = __shfl_up_sync(FULL, P, 12);
    float Pm16 = __shfl_up_sync(FULL, P, 16);
    const float K01 = (l >= 1 ) ? P - Pm1  : NULLF;
    const float K02 = (l >= 2 ) ? P - Pm2  : NULLF;
    const float K03 = (l >= 3 ) ? P - Pm3  : NULLF;
    const float K11 = (l >= 4 ) ? P - Pm4  : NULLF;
    const float K12 = (l >= 8 ) ? P - Pm8  : NULLF;
    const float K13 = (l >= 12) ? P - Pm12 : NULLF;
    const float K21 = (l >= 16) ? P - Pm16 : NULLF;

    float a0[4] = {NULLF, NULLF, NULLF, NULLF};
    float a1[4] = {NULLF, NULLF, NULLF, NULLF};
    float a0x = NULLF, a1x = NULLF;
    float lane0src = 0.0f;                  // virtual source (log 1) at t=0

    const int* tn = g_tok + n * LL;

    for (int tt = 0; tt < LL; tt += 4) {
        const int4 tk4 = *(const int4*)(tn + tt);
        const int tks[4] = {tk4.x, tk4.y, tk4.z, tk4.w};

#pragma unroll
        for (int k = 0; k < 4; k++) {
            const int tko = tks[k] * MSTRIDE;

            float atop = __shfl_up_sync(FULL, a0[3], 1);
            if (l == 0) atop = lane0src;

            // chain injections
            float b0 = lse2(atop  + cb0[0], a1[0] + cb1[0]);
            float b1 = lse2(a0[0] + cb0[1], a1[1] + cb1[1]);
            float b2 = lse2(a0[1] + cb0[2], a1[2] + cb1[2]);
            float b3 = lse2(a0[2] + cb0[3], a1[3] + cb1[3]);

            // lane aggregate injection (flattened local prefix)
            float Bs = lse5(atop + cbW0, a1[0] + cbW1, b1 + W23, b2 + wv3, b3);

            // branch-free radix-4 warp scan (W baked into K constants)
            float o1 = __shfl_up_sync(FULL, Bs, 1);
            float o2 = __shfl_up_sync(FULL, Bs, 2);
            float o3 = __shfl_up_sync(FULL, Bs, 3);
            Bs = lse4(Bs, o1 + K01, o2 + K02, o3 + K03);
            o1 = __shfl_up_sync(FULL, Bs, 4);
            o2 = __shfl_up_sync(FULL, Bs, 8);
            o3 = __shfl_up_sync(FULL, Bs, 12);
            Bs = lse4(Bs, o1 + K11, o2 + K12, o3 + K13);
            o1 = __shfl_up_sync(FULL, Bs, 16);
            Bs = lse2(Bs, o1 + K21);

            float Bex = __shfl_up_sync(FULL, Bs, 1);
            if (l == 0) Bex = NULLF;

            // per-element chain values
            float B1 = lse2(Bex + wv0, b0);
            float B2 = lse3(Bex + Wp1, b0 + wv1, b1);
            float B3 = lse4(Bex + Wp2, b0 + W12, b1 + wv2, b2);

            // emission rows (padding -> zero row at index DD)
            const float4 ea = *(const float4*)(g_Ea + tko + m0);
            const float4 ei = *(const float4*)(g_Ei + tko + m0);
            const float eax = g_Ea[tko + MM];
            const float eix = g_Ei[tko + MM];

            // new alphas
            float na00 = lse3(atop  + q00[0], a1[0] + q10[0], Bex + c0[0]) + ea.x;
            float na10 = lse3(atop  + q01[0], a1[0] + q11[0], Bex + c1[0]) + ei.x;
            float na01 = lse3(a0[0] + q00[1], a1[1] + q10[1], B1  + c0[1]) + ea.y;
            float na11 = lse3(a0[0] + q01[1], a1[1] + q11[1], B1  + c1[1]) + ei.y;
            float na02 = lse3(a0[1] + q00[2], a1[2] + q10[2], B2  + c0[2]) + ea.z;
            float na12 = lse3(a0[1] + q01[2], a1[2] + q11[2], B2  + c1[2]) + ei.z;
            float na03 = lse3(a0[2] + q00[3], a1[3] + q10[3], B3  + c0[3]) + ea.w;
            float na13 = lse3(a0[2] + q01[3], a1[3] + q11[3], B3  + c1[3]) + ei.w;
            float na0x = lse3(a0[3] + q00x, a1x + q10x, Bs + c0x) + eax;
            float na1x = lse3(a0[3] + q01x, a1x + q11x, Bs + c1x) + eix;

            a0[0] = na00; a0[1] = na01; a0[2] = na02; a0[3] = na03;
            a1[0] = na10; a1[1] = na11; a1[2] = na12; a1[3] = na13;
            a0x = na0x; a1x = na1x;
            lane0src = NULLF;
        }
    }

    // final logsumexp over all states
    float mx = fmaxf(a0x, a1x);
#pragma unroll
    for (int q = 0; q < 4; q++) mx = fmaxf(mx, fmaxf(a0[q], a1[q]));
#pragma unroll
    for (int d = 16; d; d >>= 1) mx = fmaxf(mx, __shfl_xor_sync(FULL, mx, d));

    float s = exp2f(a0x - mx) + exp2f(a1x - mx);
#pragma unroll
    for (int q = 0; q < 4; q++) s += exp2f(a0[q] - mx) + exp2f(a1[q] - mx);
#pragma unroll
    for (int d = 16; d; d >>= 1) s += __shfl_xor_sync(FULL, s, d);

    if (l == 0) out[n] = (mx + log2f(s)) * LN2;
}

// ---------------- entry point ----------------
extern "C" void kernel_launch(void* const* d_in, const int* in_sizes, int n_in,
                              void* d_out, int out_size) {
    const float* anc  = (const float*)d_in[0];  // (129, 24)
    const float* ins  = (const float*)d_in[1];  // (129, 24)
    const float* rr   = (const float*)d_in[2];  // (129, 3, 2)
    const float* uu   = (const float*)d_in[3];  // (129, 3, 2)
    const float* data = (const float*)d_in[4];  // (512, 256, 24)
    (void)in_sizes; (void)n_in; (void)out_size;

    prep<<<NN + 1, LL>>>(anc, ins, rr, uu, data);
    hmm_fwd<<<NN / 4, 128>>>((float*)d_out);
}